// round 2
// baseline (speedup 1.0000x reference)
#include <cuda_runtime.h>
#include <cstdint>

#define NN 256   // nodes
#define FF 256   // feature dim
#define BB 32    // batch
#define EE 8192  // edges

// Scratch (allocation-free): CSR of edges grouped by destination node.
__device__ int  g_row_ptr[NN + 1];
__device__ int2 g_csr[EE];   // .x = src node, .y = float bits of cos(phase)/32

// ---------------------------------------------------------------------------
// Prep: detect index width (int32 vs int64 little-endian), build dst-CSR.
// One block; E=8192 so this is tiny.
// ---------------------------------------------------------------------------
__global__ void ep_prep_kernel(const float* __restrict__ phase,
                               const int* __restrict__ src32,
                               const int* __restrict__ dst32) {
    __shared__ int s_cnt[NN];
    __shared__ int s_off[NN];
    __shared__ int s_is64;
    const int t = threadIdx.x;
    const int nt = blockDim.x;

    if (t == 0) {
        // int64 little-endian => int32 words look like [v,0,v,0,...] with v in [0,256)
        int ok = 1;
        for (int i = 0; i < 64; i++) {
            int lo = dst32[2 * i];
            int hi = dst32[2 * i + 1];
            if (hi != 0 || lo < 0 || lo >= NN) { ok = 0; break; }
        }
        s_is64 = ok;
    }
    for (int i = t; i < NN; i += nt) s_cnt[i] = 0;
    __syncthreads();
    const int is64 = s_is64;

    for (int e = t; e < EE; e += nt) {
        int d = is64 ? dst32[2 * e] : dst32[e];
        atomicAdd(&s_cnt[d], 1);
    }
    __syncthreads();

    if (t == 0) {
        int acc = 0;
        for (int i = 0; i < NN; i++) {
            g_row_ptr[i] = acc;
            s_off[i] = acc;
            acc += s_cnt[i];
        }
        g_row_ptr[NN] = acc;
    }
    __syncthreads();

    for (int e = t; e < EE; e += nt) {
        int d = is64 ? dst32[2 * e] : dst32[e];
        int s = is64 ? src32[2 * e] : src32[e];
        int pos = atomicAdd(&s_off[d], 1);
        float c = cosf(phase[s * NN + d]) * (1.0f / 32.0f);
        g_csr[pos] = make_int2(s, __float_as_int(c));
    }
}

// ---------------------------------------------------------------------------
// Compute: block = (f-tile of 4 floats) x (half of the dst-node range).
// SMEM holds the full x slice x[:, :, f0:f0+4]  (256 nodes * 32 batch * 16B =
// 128KB) so x is read from DRAM exactly once. One warp per dst node: lane =
// batch, float4 accumulator over the f-tile -> no atomics, register-resident.
// ---------------------------------------------------------------------------
__global__ void __launch_bounds__(512, 1)
ep_compute_kernel(const float* __restrict__ x,   // [B, N, F]
                  const float* __restrict__ W,   // [N, N, F]
                  float* __restrict__ out) {     // [B, N, F]
    extern __shared__ float4 s_dyn[];
    float4* s_x = s_dyn;                         // [NN * BB], index = s*32 + b
    __shared__ int s_rp[NN / 2 + 1];             // row_ptr slice for this block

    const int bx     = blockIdx.x;               // 0..127
    const int f0     = (bx >> 1) * 4;
    const int n_base = (bx & 1) * 128;
    const int t      = threadIdx.x;

    // Stage row_ptr slice.
    for (int i = t; i < NN / 2 + 1; i += 512) s_rp[i] = g_row_ptr[n_base + i];

    // Load x tile: 8192 gathered float4s.
    for (int i = t; i < NN * BB; i += 512) {
        const int s = i >> 5;
        const int b = i & 31;
        s_x[i] = __ldg(reinterpret_cast<const float4*>(
            x + (size_t)(b * NN + s) * FF + f0));
    }
    __syncthreads();

    const int warp = t >> 5;   // 0..15
    const int lane = t & 31;   // batch index

    // Each warp handles 8 dst nodes, interleaved for load balance.
    for (int k = 0; k < 8; k++) {
        const int nl  = warp + (k << 4);         // local dst index 0..127
        const int n   = n_base + nl;
        int idx       = s_rp[nl];
        const int end = s_rp[nl + 1];

        float4 a0 = make_float4(0.f, 0.f, 0.f, 0.f);
        float4 a1 = make_float4(0.f, 0.f, 0.f, 0.f);
        const float* Wn = W + (size_t)n * FF + f0;   // + s * (NN*FF)

        // Prefetch first pair of edge records.
        int2 e0, e1;
        if (idx + 2 <= end) { e0 = g_csr[idx]; e1 = g_csr[idx + 1]; }

        for (; idx + 2 <= end; ) {
            const int2 c0r = e0, c1r = e1;
            idx += 2;
            if (idx + 2 <= end) {                 // prefetch next pair
                e0 = g_csr[idx];
                e1 = g_csr[idx + 1];
            }
            const float4 w0 = __ldg(reinterpret_cast<const float4*>(
                Wn + (size_t)c0r.x * (NN * FF)));
            const float4 w1 = __ldg(reinterpret_cast<const float4*>(
                Wn + (size_t)c1r.x * (NN * FF)));
            const float4 x0 = s_x[(c0r.x << 5) + lane];
            const float4 x1 = s_x[(c1r.x << 5) + lane];
            const float c0 = __int_as_float(c0r.y);
            const float c1 = __int_as_float(c1r.y);
            a0.x = fmaf(x0.x, w0.x * c0, a0.x);
            a0.y = fmaf(x0.y, w0.y * c0, a0.y);
            a0.z = fmaf(x0.z, w0.z * c0, a0.z);
            a0.w = fmaf(x0.w, w0.w * c0, a0.w);
            a1.x = fmaf(x1.x, w1.x * c1, a1.x);
            a1.y = fmaf(x1.y, w1.y * c1, a1.y);
            a1.z = fmaf(x1.z, w1.z * c1, a1.z);
            a1.w = fmaf(x1.w, w1.w * c1, a1.w);
        }
        if (idx < end) {
            const int2 et = g_csr[idx];
            const float4 w0 = __ldg(reinterpret_cast<const float4*>(
                Wn + (size_t)et.x * (NN * FF)));
            const float4 x0 = s_x[(et.x << 5) + lane];
            const float c0 = __int_as_float(et.y);
            a0.x = fmaf(x0.x, w0.x * c0, a0.x);
            a0.y = fmaf(x0.y, w0.y * c0, a0.y);
            a0.z = fmaf(x0.z, w0.z * c0, a0.z);
            a0.w = fmaf(x0.w, w0.w * c0, a0.w);
        }

        float4 r = make_float4(a0.x + a1.x, a0.y + a1.y,
                               a0.z + a1.z, a0.w + a1.w);
        *reinterpret_cast<float4*>(out + (size_t)(lane * NN + n) * FF + f0) = r;
    }
}

// ---------------------------------------------------------------------------
extern "C" void kernel_launch(void* const* d_in, const int* in_sizes, int n_in,
                              void* d_out, int out_size) {
    const float* x     = (const float*)d_in[0];
    const float* W     = (const float*)d_in[1];
    const float* phase = (const float*)d_in[2];
    const int*   src   = (const int*)d_in[3];
    const int*   dst   = (const int*)d_in[4];
    float*       out   = (float*)d_out;

    const int smem = NN * BB * sizeof(float4);   // 131072 bytes
    cudaFuncSetAttribute(ep_compute_kernel,
                         cudaFuncAttributeMaxDynamicSharedMemorySize, smem);

    ep_prep_kernel<<<1, 512>>>(phase, src, dst);
    ep_compute_kernel<<<128, 512, smem>>>(x, W, out);
}

// round 3
// speedup vs baseline: 1.0345x; 1.0345x over previous
#include <cuda_runtime.h>
#include <cstdint>

#define NN 256   // nodes
#define FF 256   // feature dim
#define BB 32    // batch
#define EE 8192  // edges
#define CSR_CAP 12288   // EE + NN*7 = 9984 max padded entries, rounded up

// Scratch (allocation-free): padded CSR of edges grouped by destination node.
// Row lengths are padded to multiples of 8; pad entries are {src=0, w=0.0f}.
__device__ int g_row_ptr[NN + 1];
__device__ __align__(16) int2 g_csr[CSR_CAP];  // .x = src, .y = bits of cos(phase)/32

// ---------------------------------------------------------------------------
// Prep: detect index width (int32 vs int64 LE), build padded dst-CSR.
// ---------------------------------------------------------------------------
__global__ void ep_prep_kernel(const float* __restrict__ phase,
                               const int* __restrict__ src32,
                               const int* __restrict__ dst32) {
    __shared__ int s_cnt[NN];
    __shared__ int s_off[NN];
    __shared__ int s_is64;
    __shared__ int s_total;
    const int t = threadIdx.x;
    const int nt = blockDim.x;

    if (t == 0) {
        int ok = 1;
        for (int i = 0; i < 64; i++) {
            int lo = dst32[2 * i];
            int hi = dst32[2 * i + 1];
            if (hi != 0 || lo < 0 || lo >= NN) { ok = 0; break; }
        }
        s_is64 = ok;
    }
    for (int i = t; i < NN; i += nt) s_cnt[i] = 0;
    __syncthreads();
    const int is64 = s_is64;

    for (int e = t; e < EE; e += nt) {
        int d = is64 ? dst32[2 * e] : dst32[e];
        atomicAdd(&s_cnt[d], 1);
    }
    __syncthreads();

    if (t == 0) {
        int acc = 0;
        for (int i = 0; i < NN; i++) {
            g_row_ptr[i] = acc;
            s_off[i] = acc;
            acc += (s_cnt[i] + 7) & ~7;          // pad each row to multiple of 8
        }
        g_row_ptr[NN] = acc;
        s_total = acc;
    }
    __syncthreads();

    // Zero-fill the padded buffer (pads => src 0, weight 0.0 => no-op edges).
    const int total = s_total;
    for (int i = t; i < total; i += nt) g_csr[i] = make_int2(0, 0);
    __syncthreads();

    for (int e = t; e < EE; e += nt) {
        int d = is64 ? dst32[2 * e] : dst32[e];
        int s = is64 ? src32[2 * e] : src32[e];
        int pos = atomicAdd(&s_off[d], 1);
        float c = cosf(phase[s * NN + d]) * (1.0f / 32.0f);
        g_csr[pos] = make_int2(s, __float_as_int(c));
    }
}

// ---------------------------------------------------------------------------
// Compute: block = (f-tile of 4 floats) x (half of the dst-node range).
// SMEM: full x slice x[:, :, f0:f0+4] (128KB) + this block's CSR span (<80KB).
// One warp per dst node (lane = batch). 8-edge unroll -> 8 W gathers in
// flight per warp (MLP 128/SM), CSR reads from SMEM (off the critical path).
// ---------------------------------------------------------------------------
#define FMA_EDGE(acc, q_s, q_c)                                               \
    do {                                                                      \
        const float4 wv = __ldg(reinterpret_cast<const float4*>(              \
            Wn + (size_t)(q_s) * (NN * FF)));                                 \
        const float4 xv = s_x[((q_s) << 5) + lane];                           \
        const float cc = __int_as_float(q_c);                                 \
        acc.x = fmaf(xv.x, wv.x * cc, acc.x);                                 \
        acc.y = fmaf(xv.y, wv.y * cc, acc.y);                                 \
        acc.z = fmaf(xv.z, wv.z * cc, acc.z);                                 \
        acc.w = fmaf(xv.w, wv.w * cc, acc.w);                                 \
    } while (0)

__global__ void __launch_bounds__(512, 1)
ep_compute_kernel(const float* __restrict__ x,   // [B, N, F]
                  const float* __restrict__ W,   // [N, N, F]
                  float* __restrict__ out) {     // [B, N, F]
    extern __shared__ char s_raw[];
    float4* s_x  = reinterpret_cast<float4*>(s_raw);                 // [NN*BB]
    int2* s_csr  = reinterpret_cast<int2*>(s_raw + NN * BB * 16);    // span
    __shared__ int s_rp[NN / 2 + 1];

    const int bx     = blockIdx.x;               // 0..127
    const int f0     = (bx >> 1) * 4;
    const int n_base = (bx & 1) * 128;
    const int t      = threadIdx.x;

    const int cbeg = g_row_ptr[n_base];
    const int cend = g_row_ptr[n_base + 128];

    // Stage CSR span (coalesced) and row pointers.
    for (int i = t; i < cend - cbeg; i += 512) s_csr[i] = g_csr[cbeg + i];
    for (int i = t; i < NN / 2 + 1; i += 512)  s_rp[i]  = g_row_ptr[n_base + i];

    // Stage x tile: 8192 gathered float4s (x read from DRAM once per f-tile).
    for (int i = t; i < NN * BB; i += 512) {
        const int s = i >> 5;
        const int b = i & 31;
        s_x[i] = __ldg(reinterpret_cast<const float4*>(
            x + (size_t)(b * NN + s) * FF + f0));
    }
    __syncthreads();

    const int warp = t >> 5;   // 0..15
    const int lane = t & 31;   // batch index

    for (int k = 0; k < 8; k++) {
        const int nl  = warp + (k << 4);         // local dst index 0..127
        const int n   = n_base + nl;
        const int p   = s_rp[nl] - cbeg;         // multiple of 8 entries
        const int pe  = s_rp[nl + 1] - cbeg;
        const int iters = (pe - p) >> 3;         // rows padded to 8

        float4 a0 = make_float4(0.f, 0.f, 0.f, 0.f);
        float4 a1 = make_float4(0.f, 0.f, 0.f, 0.f);
        const float* Wn = W + (size_t)n * FF + f0;

        // 8-aligned row start -> int4 loads of 2 edges each.
        const int4* c4 = reinterpret_cast<const int4*>(s_csr + p);

        for (int it = 0; it < iters; it++) {
            const int4 q0 = c4[it * 4 + 0];
            const int4 q1 = c4[it * 4 + 1];
            const int4 q2 = c4[it * 4 + 2];
            const int4 q3 = c4[it * 4 + 3];
            FMA_EDGE(a0, q0.x, q0.y);
            FMA_EDGE(a1, q0.z, q0.w);
            FMA_EDGE(a0, q1.x, q1.y);
            FMA_EDGE(a1, q1.z, q1.w);
            FMA_EDGE(a0, q2.x, q2.y);
            FMA_EDGE(a1, q2.z, q2.w);
            FMA_EDGE(a0, q3.x, q3.y);
            FMA_EDGE(a1, q3.z, q3.w);
        }

        float4 r = make_float4(a0.x + a1.x, a0.y + a1.y,
                               a0.z + a1.z, a0.w + a1.w);
        *reinterpret_cast<float4*>(out + (size_t)(lane * NN + n) * FF + f0) = r;
    }
}

// ---------------------------------------------------------------------------
extern "C" void kernel_launch(void* const* d_in, const int* in_sizes, int n_in,
                              void* d_out, int out_size) {
    const float* x     = (const float*)d_in[0];
    const float* W     = (const float*)d_in[1];
    const float* phase = (const float*)d_in[2];
    const int*   src   = (const int*)d_in[3];
    const int*   dst   = (const int*)d_in[4];
    float*       out   = (float*)d_out;

    // 128KB x-tile + 80KB CSR span headroom = 212992 bytes (< 227KB limit).
    const int smem = NN * BB * 16 + 10240 * 8;
    cudaFuncSetAttribute(ep_compute_kernel,
                         cudaFuncAttributeMaxDynamicSharedMemorySize, smem);

    ep_prep_kernel<<<1, 512>>>(phase, src, dst);
    ep_compute_kernel<<<128, 512, smem>>>(x, W, out);
}